// round 15
// baseline (speedup 1.0000x reference)
#include <cuda_runtime.h>
#include <cuda_fp16.h>
#include <math.h>
#include <stdint.h>

#define NTHR 256
#define TE   64
#define DD   128
#define HH   256
#define EPSLN 1e-5f

// ---------------- smem layout (byte offsets) ----------------
#define OFF_B1S   0
#define OFF_G1S   1024
#define OFF_BE1S  2048
#define OFF_B2S   3072
#define OFF_G2S   4096
#define OFF_BE2S  5120
#define OFF_W3S   6144
#define OFF_LNEX  7168      // 64 rows x 4 quarters x float2 = 2048
#define OFF_PEX   9216      // 64 x 4 x float = 1024
#define TILES     10240
// phase 1: A1 (64x128 fp16, row stride 68 words = 272 B) ; B1 blob
#define A1S   (TILES)                  // 17408
#define B1S   (TILES + 17408)          // 65536 -> ends TILES+82944
// phase 2 (aliases phase 1): A2 (64x256 fp16, stride 132 words = 528 B) ; B2 double buffer (32K chunks)
#define A2S    (TILES)                 // 33792
#define B2BUF0 (TILES + 33792)         // 32768
#define B2BUF1 (TILES + 66560)         // 32768 -> ends TILES+99328
#define SMEM_BYTES (TILES + 99328)     // 109568  (x2 CTAs = 219136 <= 228KB)

// fragment-ordered fp16 weight blobs:
// W1 blob slot = ((ntile*8 + kstep)*32 + lane) -> 8 bytes
//   {W[n][k0],W[n][k0+1], W[n][k0+8],W[n][k0+9]}, n = ntile*8 + lane/4, k0 = kstep*16 + (lane%4)*2
__device__ __align__(16) unsigned char g_W1f[65536];
// W2 blob: [kchunk 4][ntile 32][kstep 4][lane 32] x 8B (chunk = K 64)
__device__ __align__(16) unsigned char g_W2f[131072];

__device__ __forceinline__ uint32_t pack_f16x2(float a, float b) {
    __half2 h = __floats2half2_rn(a, b);
    return *reinterpret_cast<uint32_t*>(&h);
}

__device__ __forceinline__ void mma_f16(float d[4], const uint32_t a[4], const uint32_t b[2]) {
    asm volatile(
        "mma.sync.aligned.m16n8k16.row.col.f32.f16.f16.f32 "
        "{%0,%1,%2,%3}, {%4,%5,%6,%7}, {%8,%9}, {%0,%1,%2,%3};"
        : "+f"(d[0]), "+f"(d[1]), "+f"(d[2]), "+f"(d[3])
        : "r"(a[0]), "r"(a[1]), "r"(a[2]), "r"(a[3]), "r"(b[0]), "r"(b[1]));
}

__device__ __forceinline__ void ldsm_x4(uint32_t a[4], uint32_t saddr) {
    asm volatile("ldmatrix.sync.aligned.m8n8.x4.shared.b16 {%0,%1,%2,%3}, [%4];"
                 : "=r"(a[0]), "=r"(a[1]), "=r"(a[2]), "=r"(a[3]) : "r"(saddr));
}

__device__ __forceinline__ void cp16(uint32_t dst_smem, const void* gsrc) {
    asm volatile("cp.async.cg.shared.global [%0], [%1], 16;" :: "r"(dst_smem), "l"(gsrc));
}
#define CP_COMMIT() asm volatile("cp.async.commit_group;" ::: "memory")
#define CP_WAIT(N)  asm volatile("cp.async.wait_group %0;" :: "n"(N) : "memory")

// ---------------- prep: repack weights into fragment-ordered fp16 blobs ----------------
__global__ void prep_kernel(const float* __restrict__ W1, const float* __restrict__ W2) {
    int i = blockIdx.x * blockDim.x + threadIdx.x;
    if (i < 8192) {                                    // W1 [256n][128k], 32 nt x 8 ks
        int nt = i >> 8, ks = (i >> 5) & 7, lane = i & 31;
        int n = nt * 8 + (lane >> 2);
        int k0 = ks * 16 + (lane & 3) * 2;
        const float* w = W1 + n * 128 + k0;
        ((uint2*)g_W1f)[i] = make_uint2(pack_f16x2(w[0], w[1]), pack_f16x2(w[8], w[9]));
    } else if (i < 8192 + 16384) {                     // W2 [256n][256k], 4 kc x 32 nt x 4 ks
        int j = i - 8192;
        int kc = j >> 12, nt = (j >> 7) & 31, ks = (j >> 5) & 3, lane = j & 31;
        int n = nt * 8 + (lane >> 2);
        int k0 = kc * 64 + ks * 16 + (lane & 3) * 2;
        const float* w = W2 + n * 256 + k0;
        ((uint2*)g_W2f)[j] = make_uint2(pack_f16x2(w[0], w[1]), pack_f16x2(w[8], w[9]));
    }
}

// ---------------- main ----------------
__global__ void __launch_bounds__(NTHR, 2)
mlp_mma_kernel(const float* __restrict__ h,
               const int* __restrict__ src, const int* __restrict__ dst,
               const float* __restrict__ b1, const float* __restrict__ g1, const float* __restrict__ be1,
               const float* __restrict__ b2, const float* __restrict__ g2, const float* __restrict__ be2,
               const float* __restrict__ W3, const float* __restrict__ b3,
               float* __restrict__ out, int E, int Nn)
{
    extern __shared__ __align__(16) char smem[];
    const int tid   = threadIdx.x;
    const int wid   = tid >> 5;
    const int lane  = tid & 31;
    const int rowt  = wid & 1;          // row group: rows [rowt*32, rowt*32+32)
    const int nq    = wid >> 1;         // col quarter: cols [nq*64, nq*64+64)
    const int e0    = blockIdx.x * TE;
    const uint32_t sbase = (uint32_t)__cvta_generic_to_shared(smem);

    // ldmatrix lane addressing
    const int lrow = (((lane >> 3) & 1) << 3) + (lane & 7);
    const int lkb  = ((lane >> 4) << 4);

    // --- async-stage B1 blob (65536 B) ---
    {
        uint32_t dh = sbase + B1S;
#pragma unroll
        for (int i = 0; i < 16; i++)
            cp16(dh + (tid + i * NTHR) * 16, (const char*)g_W1f + (tid + i * NTHR) * 16);
        CP_COMMIT();
    }

    // --- params ---
    {
        ((float*)(smem + OFF_B1S))[tid]  = b1[tid];
        ((float*)(smem + OFF_G1S))[tid]  = g1[tid];
        ((float*)(smem + OFF_BE1S))[tid] = be1[tid];
        ((float*)(smem + OFF_B2S))[tid]  = b2[tid];
        ((float*)(smem + OFF_G2S))[tid]  = g2[tid];
        ((float*)(smem + OFF_BE2S))[tid] = be2[tid];
        ((float*)(smem + OFF_W3S))[tid]  = W3[tid];
    }

    // --- gather x = h[src]*h[dst] -> fp16, A1 row-major (stride 68 words) ---
    {
        int row = tid >> 2, q = tid & 3;
        int eg = e0 + row;
        int si = 0, di = 0;
        if (eg < E) { si = src[eg]; di = dst[eg]; }
        if ((unsigned)si >= (unsigned)Nn) si = 0;
        if ((unsigned)di >= (unsigned)Nn) di = 0;
        const float4* ps = (const float4*)(h + (size_t)si * DD) + q * 8;
        const float4* pd = (const float4*)(h + (size_t)di * DD) + q * 8;
        uint32_t* oh = (uint32_t*)(smem + A1S) + row * 68 + q * 16;
#pragma unroll
        for (int i = 0; i < 8; i++) {
            float4 a = ps[i], b = pd[i];
            oh[i * 2]     = pack_f16x2(a.x * b.x, a.y * b.y);
            oh[i * 2 + 1] = pack_f16x2(a.z * b.z, a.w * b.w);
        }
    }
    CP_WAIT(0);
    __syncthreads();

    float acc0[8][4], acc1[8][4];
#pragma unroll
    for (int t = 0; t < 8; t++) {
        acc0[t][0]=acc0[t][1]=acc0[t][2]=acc0[t][3]=0.f;
        acc1[t][0]=acc1[t][1]=acc1[t][2]=acc1[t][3]=0.f;
    }

    const int rbase = rowt * 32 + (lane >> 2);

    // ---- layer 1: K=128, 8 ksteps, fp16, ldmatrix A ----
    {
        const uint32_t aA0 = sbase + A1S + (uint32_t)(rowt * 32 + lrow) * 272 + lkb;
        const uint32_t aA1 = aA0 + 16 * 272;
#pragma unroll 1
        for (int ks = 0; ks < 8; ks++) {
            uint32_t a0[4], a1[4];
            ldsm_x4(a0, aA0 + ks * 32);
            ldsm_x4(a1, aA1 + ks * 32);
#pragma unroll
            for (int tl = 0; tl < 8; tl++) {
                int nt = nq * 8 + tl;
                uint2 bh = *(const uint2*)(smem + B1S + (size_t)((nt * 8 + ks) * 32 + lane) * 8);
                mma_f16(acc0[tl], a0, (const uint32_t*)&bh);
                mma_f16(acc1[tl], a1, (const uint32_t*)&bh);
            }
        }
    }

    const int r0 = rbase, r1 = rbase + 8, r2 = rbase + 16, r3 = rbase + 24;
    const float* b1s  = (const float*)(smem + OFF_B1S);
    const float* g1s  = (const float*)(smem + OFF_G1S);
    const float* be1s = (const float*)(smem + OFF_BE1S);
    float2* lnex = (float2*)(smem + OFF_LNEX);

    // ---- epilogue 1: bias + partial LN stats (per col-quarter) ----
    {
        float sa=0.f,s2a=0.f, sb=0.f,s2b=0.f, sc=0.f,s2c=0.f, sd=0.f,s2d=0.f;
#pragma unroll
        for (int tl = 0; tl < 8; tl++) {
            int c0 = nq * 64 + tl * 8 + (lane & 3) * 2;
            float bb0 = b1s[c0], bb1 = b1s[c0 + 1];
            acc0[tl][0] += bb0; acc0[tl][1] += bb1; acc0[tl][2] += bb0; acc0[tl][3] += bb1;
            acc1[tl][0] += bb0; acc1[tl][1] += bb1; acc1[tl][2] += bb0; acc1[tl][3] += bb1;
            sa += acc0[tl][0] + acc0[tl][1]; s2a += acc0[tl][0]*acc0[tl][0] + acc0[tl][1]*acc0[tl][1];
            sb += acc0[tl][2] + acc0[tl][3]; s2b += acc0[tl][2]*acc0[tl][2] + acc0[tl][3]*acc0[tl][3];
            sc += acc1[tl][0] + acc1[tl][1]; s2c += acc1[tl][0]*acc1[tl][0] + acc1[tl][1]*acc1[tl][1];
            sd += acc1[tl][2] + acc1[tl][3]; s2d += acc1[tl][2]*acc1[tl][2] + acc1[tl][3]*acc1[tl][3];
        }
#pragma unroll
        for (int o = 1; o <= 2; o <<= 1) {
            sa += __shfl_xor_sync(0xffffffffu, sa, o);  s2a += __shfl_xor_sync(0xffffffffu, s2a, o);
            sb += __shfl_xor_sync(0xffffffffu, sb, o);  s2b += __shfl_xor_sync(0xffffffffu, s2b, o);
            sc += __shfl_xor_sync(0xffffffffu, sc, o);  s2c += __shfl_xor_sync(0xffffffffu, s2c, o);
            sd += __shfl_xor_sync(0xffffffffu, sd, o);  s2d += __shfl_xor_sync(0xffffffffu, s2d, o);
        }
        if ((lane & 3) == 0) {
            lnex[r0 * 4 + nq] = make_float2(sa, s2a);
            lnex[r1 * 4 + nq] = make_float2(sb, s2b);
            lnex[r2 * 4 + nq] = make_float2(sc, s2c);
            lnex[r3 * 4 + nq] = make_float2(sd, s2d);
        }
    }
    __syncthreads();   // A1/B1 now dead

    // prefetch W2 chunk 0 (32768 B) into buf0
    {
        uint32_t d0 = sbase + B2BUF0;
#pragma unroll
        for (int i = 0; i < 8; i++)
            cp16(d0 + (tid + i * NTHR) * 16, (const char*)g_W2f + (tid + i * NTHR) * 16);
        CP_COMMIT();
    }

    // ---- LN1 transform + ReLU -> A2 fp16 (stride 132 words) ----
    {
        float mu[4], rs[4];
        int rr[4] = {r0, r1, r2, r3};
#pragma unroll
        for (int k = 0; k < 4; k++) {
            float2 q0 = lnex[rr[k] * 4 + 0], q1 = lnex[rr[k] * 4 + 1];
            float2 q2 = lnex[rr[k] * 4 + 2], q3 = lnex[rr[k] * 4 + 3];
            float s  = q0.x + q1.x + q2.x + q3.x;
            float s2 = q0.y + q1.y + q2.y + q3.y;
            mu[k] = s * (1.f / HH);
            rs[k] = rsqrtf(s2 * (1.f / HH) - mu[k] * mu[k] + EPSLN);
        }
        uint32_t* A2w = (uint32_t*)(smem + A2S);
#pragma unroll
        for (int tl = 0; tl < 8; tl++) {
            int c0 = nq * 64 + tl * 8 + (lane & 3) * 2;
            float ga = g1s[c0], gb = g1s[c0 + 1], ba = be1s[c0], bb = be1s[c0 + 1];
            int w = c0 >> 1;
            A2w[r0 * 132 + w] = pack_f16x2(
                fmaxf((acc0[tl][0] - mu[0]) * rs[0] * ga + ba, 0.f),
                fmaxf((acc0[tl][1] - mu[0]) * rs[0] * gb + bb, 0.f));
            A2w[r1 * 132 + w] = pack_f16x2(
                fmaxf((acc0[tl][2] - mu[1]) * rs[1] * ga + ba, 0.f),
                fmaxf((acc0[tl][3] - mu[1]) * rs[1] * gb + bb, 0.f));
            A2w[r2 * 132 + w] = pack_f16x2(
                fmaxf((acc1[tl][0] - mu[2]) * rs[2] * ga + ba, 0.f),
                fmaxf((acc1[tl][1] - mu[2]) * rs[2] * gb + bb, 0.f));
            A2w[r3 * 132 + w] = pack_f16x2(
                fmaxf((acc1[tl][2] - mu[3]) * rs[3] * ga + ba, 0.f),
                fmaxf((acc1[tl][3] - mu[3]) * rs[3] * gb + bb, 0.f));
        }
    }

#pragma unroll
    for (int t = 0; t < 8; t++) {
        acc0[t][0]=acc0[t][1]=acc0[t][2]=acc0[t][3]=0.f;
        acc1[t][0]=acc1[t][1]=acc1[t][2]=acc1[t][3]=0.f;
    }

    // ---- layer 2: K=256 in 4 chunks of 64, double-buffered cp.async ----
    {
        const uint32_t aB0 = sbase + A2S + (uint32_t)(rowt * 32 + lrow) * 528 + lkb;
        const uint32_t aB1 = aB0 + 16 * 528;
#pragma unroll 1
        for (int kc = 0; kc < 4; kc++) {
            __syncthreads();   // prior reads of the buffer being overwritten are done
            if (kc < 3) {
                uint32_t d = sbase + (((kc + 1) & 1) ? B2BUF1 : B2BUF0);
                const char* sh = (const char*)g_W2f + (kc + 1) * 32768;
#pragma unroll
                for (int i = 0; i < 8; i++)
                    cp16(d + (tid + i * NTHR) * 16, sh + (tid + i * NTHR) * 16);
                CP_COMMIT();
                CP_WAIT(1);    // chunk kc has landed
            } else {
                CP_WAIT(0);
            }
            __syncthreads();   // chunk kc visible to all warps
            const char* buf = smem + ((kc & 1) ? B2BUF1 : B2BUF0);
#pragma unroll
            for (int ks = 0; ks < 4; ks++) {
                int gk = kc * 4 + ks;
                uint32_t a0[4], a1[4];
                ldsm_x4(a0, aB0 + gk * 32);
                ldsm_x4(a1, aB1 + gk * 32);
#pragma unroll
                for (int tl = 0; tl < 8; tl++) {
                    int nt = nq * 8 + tl;
                    uint2 bh = *(const uint2*)(buf + (size_t)((nt * 4 + ks) * 32 + lane) * 8);
                    mma_f16(acc0[tl], a0, (const uint32_t*)&bh);
                    mma_f16(acc1[tl], a1, (const uint32_t*)&bh);
                }
            }
        }
    }

    // ---- epilogue 2: bias + partial LN stats ----
    const float* b2s  = (const float*)(smem + OFF_B2S);
    const float* g2s  = (const float*)(smem + OFF_G2S);
    const float* be2s = (const float*)(smem + OFF_BE2S);
    const float* w3s  = (const float*)(smem + OFF_W3S);
    {
        float sa=0.f,s2a=0.f, sb=0.f,s2b=0.f, sc=0.f,s2c=0.f, sd=0.f,s2d=0.f;
#pragma unroll
        for (int tl = 0; tl < 8; tl++) {
            int c0 = nq * 64 + tl * 8 + (lane & 3) * 2;
            float bb0 = b2s[c0], bb1 = b2s[c0 + 1];
            acc0[tl][0] += bb0; acc0[tl][1] += bb1; acc0[tl][2] += bb0; acc0[tl][3] += bb1;
            acc1[tl][0] += bb0; acc1[tl][1] += bb1; acc1[tl][2] += bb0; acc1[tl][3] += bb1;
            sa += acc0[tl][0] + acc0[tl][1]; s2a += acc0[tl][0]*acc0[tl][0] + acc0[tl][1]*acc0[tl][1];
            sb += acc0[tl][2] + acc0[tl][3]; s2b += acc0[tl][2]*acc0[tl][2] + acc0[tl][3]*acc0[tl][3];
            sc += acc1[tl][0] + acc1[tl][1]; s2c += acc1[tl][0]*acc1[tl][0] + acc1[tl][1]*acc1[tl][1];
            sd += acc1[tl][2] + acc1[tl][3]; s2d += acc1[tl][2]*acc1[tl][2] + acc1[tl][3]*acc1[tl][3];
        }
#pragma unroll
        for (int o = 1; o <= 2; o <<= 1) {
            sa += __shfl_xor_sync(0xffffffffu, sa, o);  s2a += __shfl_xor_sync(0xffffffffu, s2a, o);
            sb += __shfl_xor_sync(0xffffffffu, sb, o);  s2b += __shfl_xor_sync(0xffffffffu, s2b, o);
            sc += __shfl_xor_sync(0xffffffffu, sc, o);  s2c += __shfl_xor_sync(0xffffffffu, s2c, o);
            sd += __shfl_xor_sync(0xffffffffu, sd, o);  s2d += __shfl_xor_sync(0xffffffffu, s2d, o);
        }
        if ((lane & 3) == 0) {
            lnex[r0 * 4 + nq] = make_float2(sa, s2a);
            lnex[r1 * 4 + nq] = make_float2(sb, s2b);
            lnex[r2 * 4 + nq] = make_float2(sc, s2c);
            lnex[r3 * 4 + nq] = make_float2(sd, s2d);
        }
    }
    __syncthreads();
    // ---- LN2 + ReLU + dot W3 partials ----
    {
        float mu[4], rs[4];
        int rr[4] = {r0, r1, r2, r3};
#pragma unroll
        for (int k = 0; k < 4; k++) {
            float2 q0 = lnex[rr[k] * 4 + 0], q1 = lnex[rr[k] * 4 + 1];
            float2 q2 = lnex[rr[k] * 4 + 2], q3 = lnex[rr[k] * 4 + 3];
            float s  = q0.x + q1.x + q2.x + q3.x;
            float s2 = q0.y + q1.y + q2.y + q3.y;
            mu[k] = s * (1.f / HH);
            rs[k] = rsqrtf(s2 * (1.f / HH) - mu[k] * mu[k] + EPSLN);
        }
        float pa = 0.f, pb = 0.f, pc = 0.f, pd = 0.f;
#pragma unroll
        for (int tl = 0; tl < 8; tl++) {
            int c0 = nq * 64 + tl * 8 + (lane & 3) * 2;
            float ga = g2s[c0], gb = g2s[c0 + 1], ba = be2s[c0], bb = be2s[c0 + 1];
            float w0 = w3s[c0], w1 = w3s[c0 + 1];
            pa = fmaf(fmaxf((acc0[tl][0] - mu[0]) * rs[0] * ga + ba, 0.f), w0, pa);
            pa = fmaf(fmaxf((acc0[tl][1] - mu[0]) * rs[0] * gb + bb, 0.f), w1, pa);
            pb = fmaf(fmaxf((acc0[tl][2] - mu[1]) * rs[1] * ga + ba, 0.f), w0, pb);
            pb = fmaf(fmaxf((acc0[tl][3] - mu[1]) * rs[1] * gb + bb, 0.f), w1, pb);
            pc = fmaf(fmaxf((acc1[tl][0] - mu[2]) * rs[2] * ga + ba, 0.f), w0, pc);
            pc = fmaf(fmaxf((acc1[tl][1] - mu[2]) * rs[2] * gb + bb, 0.f), w1, pc);
            pd = fmaf(fmaxf((acc1[tl][2] - mu[3]) * rs[3] * ga + ba, 0.f), w0, pd);
            pd = fmaf(fmaxf((acc1[tl][3] - mu[3]) * rs[3] * gb + bb, 0.f), w1, pd);
        }
#pragma unroll
        for (int o = 1; o <= 2; o <<= 1) {
            pa += __shfl_xor_sync(0xffffffffu, pa, o);
            pb += __shfl_xor_sync(0xffffffffu, pb, o);
            pc += __shfl_xor_sync(0xffffffffu, pc, o);
            pd += __shfl_xor_sync(0xffffffffu, pd, o);
        }
        float* pex = (float*)(smem + OFF_PEX);
        if ((lane & 3) == 0) {
            pex[r0 * 4 + nq] = pa;
            pex[r1 * 4 + nq] = pb;
            pex[r2 * 4 + nq] = pc;
            pex[r3 * 4 + nq] = pd;
        }
    }
    __syncthreads();
    if (tid < TE) {
        float* pex = (float*)(smem + OFF_PEX);
        float p = pex[tid * 4] + pex[tid * 4 + 1] + pex[tid * 4 + 2] + pex[tid * 4 + 3] + b3[0];
        int eg = e0 + tid;
        if (eg < E) out[eg] = 1.f / (1.f + expf(-p));
    }
}

extern "C" void kernel_launch(void* const* d_in, const int* in_sizes, int n_in,
                              void* d_out, int out_size)
{
    const float* h   = (const float*)d_in[0];
    const int*   src = (const int*)d_in[1];
    const int*   dst = (const int*)d_in[2];
    const float* W1 = (const float*)d_in[3];  const float* b1 = (const float*)d_in[4];
    const float* g1 = (const float*)d_in[5];  const float* be1 = (const float*)d_in[6];
    const float* W2 = (const float*)d_in[7];  const float* b2 = (const float*)d_in[8];
    const float* g2 = (const float*)d_in[9];  const float* be2 = (const float*)d_in[10];
    const float* W3 = (const float*)d_in[11]; const float* b3 = (const float*)d_in[12];

    int E  = in_sizes[1];
    int Nn = in_sizes[0] / DD;

    prep_kernel<<<(8192 + 16384 + 255) / 256, 256>>>(W1, W2);

    cudaFuncSetAttribute(mlp_mma_kernel,
                         cudaFuncAttributeMaxDynamicSharedMemorySize, SMEM_BYTES);
    int grid = (E + TE - 1) / TE;
    mlp_mma_kernel<<<grid, NTHR, SMEM_BYTES>>>(
        h, src, dst, b1, g1, be1, b2, g2, be2, W3, b3,
        (float*)d_out, E, Nn);
}

// round 16
// speedup vs baseline: 1.0715x; 1.0715x over previous
#include <cuda_runtime.h>
#include <cuda_fp16.h>
#include <math.h>
#include <stdint.h>

#define NTHR 256
#define TE   64
#define DD   128
#define HH   256
#define EPSLN 1e-5f

// ---------------- smem layout (byte offsets) ----------------
#define OFF_B1S   0
#define OFF_G1S   1024
#define OFF_BE1S  2048
#define OFF_B2S   3072
#define OFF_G2S   4096
#define OFF_BE2S  5120
#define OFF_W3S   6144
#define OFF_LNEX  7168      // 64 rows x 4 quarters x float2 = 2048
#define OFF_PEX   9216      // 64 x 4 x float = 1024
#define TILES     10240
// phase 1: A1 (64x128 fp16, row stride 68 words = 272 B) ; B1 blob
#define A1S   (TILES)                  // 17408
#define B1S   (TILES + 17408)          // 65536 -> ends TILES+82944
// phase 2 (aliases phase 1): A2 (64x256 fp16, stride 132 words = 528 B) ; B2 double buffer
#define A2S    (TILES)                 // 33792
#define B2BUF0 (TILES + 33792)         // 16384
#define B2BUF1 (TILES + 50176)         // 16384 -> ends TILES+66560
#define SMEM_BYTES (TILES + 82944)     // 93184  (x2 CTAs = 186368 <= 228KB)

// fragment-ordered fp16 weight blobs:
// W1 blob slot = ((ntile*8 + kstep)*32 + lane) -> 8 bytes
//   {W[n][k0],W[n][k0+1], W[n][k0+8],W[n][k0+9]}, n = ntile*8 + lane/4, k0 = kstep*16 + (lane%4)*2
__device__ __align__(16) unsigned char g_W1f[65536];
// W2 blob: [kchunk 8][ntile 32][kstep 2][lane 32] x 8B (chunk = K 32)
__device__ __align__(16) unsigned char g_W2f[131072];

__device__ __forceinline__ uint32_t pack_f16x2(float a, float b) {
    __half2 h = __floats2half2_rn(a, b);
    return *reinterpret_cast<uint32_t*>(&h);
}

__device__ __forceinline__ void mma_f16(float d[4], const uint32_t a[4], const uint32_t b[2]) {
    asm volatile(
        "mma.sync.aligned.m16n8k16.row.col.f32.f16.f16.f32 "
        "{%0,%1,%2,%3}, {%4,%5,%6,%7}, {%8,%9}, {%0,%1,%2,%3};"
        : "+f"(d[0]), "+f"(d[1]), "+f"(d[2]), "+f"(d[3])
        : "r"(a[0]), "r"(a[1]), "r"(a[2]), "r"(a[3]), "r"(b[0]), "r"(b[1]));
}

__device__ __forceinline__ void ldsm_x4(uint32_t a[4], uint32_t saddr) {
    asm volatile("ldmatrix.sync.aligned.m8n8.x4.shared.b16 {%0,%1,%2,%3}, [%4];"
                 : "=r"(a[0]), "=r"(a[1]), "=r"(a[2]), "=r"(a[3]) : "r"(saddr));
}

__device__ __forceinline__ void cp16(uint32_t dst_smem, const void* gsrc) {
    asm volatile("cp.async.cg.shared.global [%0], [%1], 16;" :: "r"(dst_smem), "l"(gsrc));
}
#define CP_COMMIT() asm volatile("cp.async.commit_group;" ::: "memory")
#define CP_WAIT(N)  asm volatile("cp.async.wait_group %0;" :: "n"(N) : "memory")

// ---------------- prep: repack weights into fragment-ordered fp16 blobs ----------------
__global__ void prep_kernel(const float* __restrict__ W1, const float* __restrict__ W2) {
    int i = blockIdx.x * blockDim.x + threadIdx.x;
    if (i < 8192) {                                    // W1 [256n][128k], 32 nt x 8 ks
        int nt = i >> 8, ks = (i >> 5) & 7, lane = i & 31;
        int n = nt * 8 + (lane >> 2);
        int k0 = ks * 16 + (lane & 3) * 2;
        const float* w = W1 + n * 128 + k0;
        ((uint2*)g_W1f)[i] = make_uint2(pack_f16x2(w[0], w[1]), pack_f16x2(w[8], w[9]));
    } else if (i < 8192 + 16384) {                     // W2 [256n][256k], 8 kc x 32 nt x 2 ks
        int j = i - 8192;
        int kc = j >> 11, nt = (j >> 6) & 31, ks = (j >> 5) & 1, lane = j & 31;
        int n = nt * 8 + (lane >> 2);
        int k0 = kc * 32 + ks * 16 + (lane & 3) * 2;
        const float* w = W2 + n * 256 + k0;
        ((uint2*)g_W2f)[j] = make_uint2(pack_f16x2(w[0], w[1]), pack_f16x2(w[8], w[9]));
    }
}

// ---------------- main ----------------
__global__ void __launch_bounds__(NTHR, 2)
mlp_mma_kernel(const float* __restrict__ h,
               const int* __restrict__ src, const int* __restrict__ dst,
               const float* __restrict__ b1, const float* __restrict__ g1, const float* __restrict__ be1,
               const float* __restrict__ b2, const float* __restrict__ g2, const float* __restrict__ be2,
               const float* __restrict__ W3, const float* __restrict__ b3,
               float* __restrict__ out, int E, int Nn)
{
    extern __shared__ __align__(16) char smem[];
    const int tid   = threadIdx.x;
    const int wid   = tid >> 5;
    const int lane  = tid & 31;
    const int rowt  = wid & 1;          // row group: rows [rowt*32, rowt*32+32)
    const int nq    = wid >> 1;         // col quarter: cols [nq*64, nq*64+64)
    const int e0    = blockIdx.x * TE;
    const uint32_t sbase = (uint32_t)__cvta_generic_to_shared(smem);

    // ldmatrix lane addressing
    const int lrow = (((lane >> 3) & 1) << 3) + (lane & 7);
    const int lkb  = ((lane >> 4) << 4);

    // --- async-stage B1 blob (65536 B) ---
    {
        uint32_t dh = sbase + B1S;
#pragma unroll
        for (int i = 0; i < 16; i++)
            cp16(dh + (tid + i * NTHR) * 16, (const char*)g_W1f + (tid + i * NTHR) * 16);
        CP_COMMIT();
    }

    // --- params (256 threads, 256 entries each) ---
    {
        ((float*)(smem + OFF_B1S))[tid]  = b1[tid];
        ((float*)(smem + OFF_G1S))[tid]  = g1[tid];
        ((float*)(smem + OFF_BE1S))[tid] = be1[tid];
        ((float*)(smem + OFF_B2S))[tid]  = b2[tid];
        ((float*)(smem + OFF_G2S))[tid]  = g2[tid];
        ((float*)(smem + OFF_BE2S))[tid] = be2[tid];
        ((float*)(smem + OFF_W3S))[tid]  = W3[tid];
    }

    // --- gather x = h[src]*h[dst] -> fp16, A1 row-major (stride 68 words) ---
    {
        int row = tid >> 2, q = tid & 3;          // 64 rows x 4 quarters
        int eg = e0 + row;
        int si = 0, di = 0;
        if (eg < E) { si = src[eg]; di = dst[eg]; }
        if ((unsigned)si >= (unsigned)Nn) si = 0;
        if ((unsigned)di >= (unsigned)Nn) di = 0;
        const float4* ps = (const float4*)(h + (size_t)si * DD) + q * 8;
        const float4* pd = (const float4*)(h + (size_t)di * DD) + q * 8;
        uint32_t* oh = (uint32_t*)(smem + A1S) + row * 68 + q * 16;
#pragma unroll
        for (int i = 0; i < 8; i++) {
            float4 a = ps[i], b = pd[i];
            oh[i * 2]     = pack_f16x2(a.x * b.x, a.y * b.y);
            oh[i * 2 + 1] = pack_f16x2(a.z * b.z, a.w * b.w);
        }
    }
    CP_WAIT(0);
    __syncthreads();

    float acc0[8][4], acc1[8][4];
#pragma unroll
    for (int t = 0; t < 8; t++) {
        acc0[t][0]=acc0[t][1]=acc0[t][2]=acc0[t][3]=0.f;
        acc1[t][0]=acc1[t][1]=acc1[t][2]=acc1[t][3]=0.f;
    }

    const int rbase = rowt * 32 + (lane >> 2);

    // ---- layer 1: K=128, 8 ksteps, fp16, ldmatrix A ----
    {
        const uint32_t aA0 = sbase + A1S + (uint32_t)(rowt * 32 + lrow) * 272 + lkb;
        const uint32_t aA1 = aA0 + 16 * 272;
#pragma unroll 1
        for (int ks = 0; ks < 8; ks++) {
            uint32_t a0[4], a1[4];
            ldsm_x4(a0, aA0 + ks * 32);
            ldsm_x4(a1, aA1 + ks * 32);
#pragma unroll
            for (int tl = 0; tl < 8; tl++) {
                int nt = nq * 8 + tl;
                uint2 bh = *(const uint2*)(smem + B1S + (size_t)((nt * 8 + ks) * 32 + lane) * 8);
                mma_f16(acc0[tl], a0, (const uint32_t*)&bh);
                mma_f16(acc1[tl], a1, (const uint32_t*)&bh);
            }
        }
    }

    const int r0 = rbase, r1 = rbase + 8, r2 = rbase + 16, r3 = rbase + 24;
    const float* b1s  = (const float*)(smem + OFF_B1S);
    const float* g1s  = (const float*)(smem + OFF_G1S);
    const float* be1s = (const float*)(smem + OFF_BE1S);
    float2* lnex = (float2*)(smem + OFF_LNEX);

    // ---- epilogue 1: bias + partial LN stats (per col-quarter) ----
    {
        float sa=0.f,s2a=0.f, sb=0.f,s2b=0.f, sc=0.f,s2c=0.f, sd=0.f,s2d=0.f;
#pragma unroll
        for (int tl = 0; tl < 8; tl++) {
            int c0 = nq * 64 + tl * 8 + (lane & 3) * 2;
            float bb0 = b1s[c0], bb1 = b1s[c0 + 1];
            acc0[tl][0] += bb0; acc0[tl][1] += bb1; acc0[tl][2] += bb0; acc0[tl][3] += bb1;
            acc1[tl][0] += bb0; acc1[tl][1] += bb1; acc1[tl][2] += bb0; acc1[tl][3] += bb1;
            sa += acc0[tl][0] + acc0[tl][1]; s2a += acc0[tl][0]*acc0[tl][0] + acc0[tl][1]*acc0[tl][1];
            sb += acc0[tl][2] + acc0[tl][3]; s2b += acc0[tl][2]*acc0[tl][2] + acc0[tl][3]*acc0[tl][3];
            sc += acc1[tl][0] + acc1[tl][1]; s2c += acc1[tl][0]*acc1[tl][0] + acc1[tl][1]*acc1[tl][1];
            sd += acc1[tl][2] + acc1[tl][3]; s2d += acc1[tl][2]*acc1[tl][2] + acc1[tl][3]*acc1[tl][3];
        }
#pragma unroll
        for (int o = 1; o <= 2; o <<= 1) {
            sa += __shfl_xor_sync(0xffffffffu, sa, o);  s2a += __shfl_xor_sync(0xffffffffu, s2a, o);
            sb += __shfl_xor_sync(0xffffffffu, sb, o);  s2b += __shfl_xor_sync(0xffffffffu, s2b, o);
            sc += __shfl_xor_sync(0xffffffffu, sc, o);  s2c += __shfl_xor_sync(0xffffffffu, s2c, o);
            sd += __shfl_xor_sync(0xffffffffu, sd, o);  s2d += __shfl_xor_sync(0xffffffffu, s2d, o);
        }
        if ((lane & 3) == 0) {
            lnex[r0 * 4 + nq] = make_float2(sa, s2a);
            lnex[r1 * 4 + nq] = make_float2(sb, s2b);
            lnex[r2 * 4 + nq] = make_float2(sc, s2c);
            lnex[r3 * 4 + nq] = make_float2(sd, s2d);
        }
    }
    __syncthreads();   // A1/B1 now dead

    // prefetch W2 chunk 0 into buf0
    {
        uint32_t d0 = sbase + B2BUF0;
#pragma unroll
        for (int i = 0; i < 4; i++)
            cp16(d0 + (tid + i * NTHR) * 16, (const char*)g_W2f + (tid + i * NTHR) * 16);
        CP_COMMIT();
    }

    // ---- LN1 transform + ReLU -> A2 fp16 (stride 132 words) ----
    {
        float mu[4], rs[4];
        int rr[4] = {r0, r1, r2, r3};
#pragma unroll
        for (int k = 0; k < 4; k++) {
            float2 q0 = lnex[rr[k] * 4 + 0], q1 = lnex[rr[k] * 4 + 1];
            float2 q2 = lnex[rr[k] * 4 + 2], q3 = lnex[rr[k] * 4 + 3];
            float s  = q0.x + q1.x + q2.x + q3.x;
            float s2 = q0.y + q1.y + q2.y + q3.y;
            mu[k] = s * (1.f / HH);
            rs[k] = rsqrtf(s2 * (1.f / HH) - mu[k] * mu[k] + EPSLN);
        }
        uint32_t* A2w = (uint32_t*)(smem + A2S);
#pragma unroll
        for (int tl = 0; tl < 8; tl++) {
            int c0 = nq * 64 + tl * 8 + (lane & 3) * 2;
            float ga = g1s[c0], gb = g1s[c0 + 1], ba = be1s[c0], bb = be1s[c0 + 1];
            int w = c0 >> 1;
            A2w[r0 * 132 + w] = pack_f16x2(
                fmaxf((acc0[tl][0] - mu[0]) * rs[0] * ga + ba, 0.f),
                fmaxf((acc0[tl][1] - mu[0]) * rs[0] * gb + bb, 0.f));
            A2w[r1 * 132 + w] = pack_f16x2(
                fmaxf((acc0[tl][2] - mu[1]) * rs[1] * ga + ba, 0.f),
                fmaxf((acc0[tl][3] - mu[1]) * rs[1] * gb + bb, 0.f));
            A2w[r2 * 132 + w] = pack_f16x2(
                fmaxf((acc1[tl][0] - mu[2]) * rs[2] * ga + ba, 0.f),
                fmaxf((acc1[tl][1] - mu[2]) * rs[2] * gb + bb, 0.f));
            A2w[r3 * 132 + w] = pack_f16x2(
                fmaxf((acc1[tl][2] - mu[3]) * rs[3] * ga + ba, 0.f),
                fmaxf((acc1[tl][3] - mu[3]) * rs[3] * gb + bb, 0.f));
        }
    }

#pragma unroll
    for (int t = 0; t < 8; t++) {
        acc0[t][0]=acc0[t][1]=acc0[t][2]=acc0[t][3]=0.f;
        acc1[t][0]=acc1[t][1]=acc1[t][2]=acc1[t][3]=0.f;
    }

    // ---- layer 2: K=256 in 8 chunks of 32, double-buffered cp.async ----
    {
        const uint32_t aB0 = sbase + A2S + (uint32_t)(rowt * 32 + lrow) * 528 + lkb;
        const uint32_t aB1 = aB0 + 16 * 528;
#pragma unroll 1
        for (int kc = 0; kc < 8; kc++) {
            __syncthreads();   // prior reads of the buffer being overwritten are done
            if (kc < 7) {
                uint32_t d = sbase + (((kc + 1) & 1) ? B2BUF1 : B2BUF0);
                const char* sh = (const char*)g_W2f + (kc + 1) * 16384;
#pragma unroll
                for (int i = 0; i < 4; i++)
                    cp16(d + (tid + i * NTHR) * 16, sh + (tid + i * NTHR) * 16);
                CP_COMMIT();
                CP_WAIT(1);    // chunk kc has landed
            } else {
                CP_WAIT(0);
            }
            __syncthreads();   // chunk kc visible to all warps
            const char* buf = smem + ((kc & 1) ? B2BUF1 : B2BUF0);
#pragma unroll
            for (int ks = 0; ks < 2; ks++) {
                int gk = kc * 2 + ks;
                uint32_t a0[4], a1[4];
                ldsm_x4(a0, aB0 + gk * 32);
                ldsm_x4(a1, aB1 + gk * 32);
#pragma unroll
                for (int tl = 0; tl < 8; tl++) {
                    int nt = nq * 8 + tl;
                    uint2 bh = *(const uint2*)(buf + (size_t)((nt * 2 + ks) * 32 + lane) * 8);
                    mma_f16(acc0[tl], a0, (const uint32_t*)&bh);
                    mma_f16(acc1[tl], a1, (const uint32_t*)&bh);
                }
            }
        }
    }

    // ---- epilogue 2: bias + partial LN stats ----
    const float* b2s  = (const float*)(smem + OFF_B2S);
    const float* g2s  = (const float*)(smem + OFF_G2S);
    const float* be2s = (const float*)(smem + OFF_BE2S);
    const float* w3s  = (const float*)(smem + OFF_W3S);
    {
        float sa=0.f,s2a=0.f, sb=0.f,s2b=0.f, sc=0.f,s2c=0.f, sd=0.f,s2d=0.f;
#pragma unroll
        for (int tl = 0; tl < 8; tl++) {
            int c0 = nq * 64 + tl * 8 + (lane & 3) * 2;
            float bb0 = b2s[c0], bb1 = b2s[c0 + 1];
            acc0[tl][0] += bb0; acc0[tl][1] += bb1; acc0[tl][2] += bb0; acc0[tl][3] += bb1;
            acc1[tl][0] += bb0; acc1[tl][1] += bb1; acc1[tl][2] += bb0; acc1[tl][3] += bb1;
            sa += acc0[tl][0] + acc0[tl][1]; s2a += acc0[tl][0]*acc0[tl][0] + acc0[tl][1]*acc0[tl][1];
            sb += acc0[tl][2] + acc0[tl][3]; s2b += acc0[tl][2]*acc0[tl][2] + acc0[tl][3]*acc0[tl][3];
            sc += acc1[tl][0] + acc1[tl][1]; s2c += acc1[tl][0]*acc1[tl][0] + acc1[tl][1]*acc1[tl][1];
            sd += acc1[tl][2] + acc1[tl][3]; s2d += acc1[tl][2]*acc1[tl][2] + acc1[tl][3]*acc1[tl][3];
        }
#pragma unroll
        for (int o = 1; o <= 2; o <<= 1) {
            sa += __shfl_xor_sync(0xffffffffu, sa, o);  s2a += __shfl_xor_sync(0xffffffffu, s2a, o);
            sb += __shfl_xor_sync(0xffffffffu, sb, o);  s2b += __shfl_xor_sync(0xffffffffu, s2b, o);
            sc += __shfl_xor_sync(0xffffffffu, sc, o);  s2c += __shfl_xor_sync(0xffffffffu, s2c, o);
            sd += __shfl_xor_sync(0xffffffffu, sd, o);  s2d += __shfl_xor_sync(0xffffffffu, s2d, o);
        }
        if ((lane & 3) == 0) {
            lnex[r0 * 4 + nq] = make_float2(sa, s2a);
            lnex[r1 * 4 + nq] = make_float2(sb, s2b);
            lnex[r2 * 4 + nq] = make_float2(sc, s2c);
            lnex[r3 * 4 + nq] = make_float2(sd, s2d);
        }
    }
    __syncthreads();
    // ---- LN2 + ReLU + dot W3 partials ----
    {
        float mu[4], rs[4];
        int rr[4] = {r0, r1, r2, r3};
#pragma unroll
        for (int k = 0; k < 4; k++) {
            float2 q0 = lnex[rr[k] * 4 + 0], q1 = lnex[rr[k] * 4 + 1];
            float2 q2 = lnex[rr[k] * 4 + 2], q3 = lnex[rr[k] * 4 + 3];
            float s  = q0.x + q1.x + q2.x + q3.x;
            float s2 = q0.y + q1.y + q2.y + q3.y;
            mu[k] = s * (1.f / HH);
            rs[k] = rsqrtf(s2 * (1.f / HH) - mu[k] * mu[k] + EPSLN);
        }
        float pa = 0.f, pb = 0.f, pc = 0.f, pd = 0.f;
#pragma unroll
        for (int tl = 0; tl < 8; tl++) {
            int c0 = nq * 64 + tl * 8 + (lane & 3) * 2;
            float ga = g2s[c0], gb = g2s[c0 + 1], ba = be2s[c0], bb = be2s[c0 + 1];
            float w0 = w3s[c0], w1 = w3s[c0 + 1];
            pa = fmaf(fmaxf((acc0[tl][0] - mu[0]) * rs[0] * ga + ba, 0.f), w0, pa);
            pa = fmaf(fmaxf((acc0[tl][1] - mu[0]) * rs[0] * gb + bb, 0.f), w1, pa);
            pb = fmaf(fmaxf((acc0[tl][2] - mu[1]) * rs[1] * ga + ba, 0.f), w0, pb);
            pb = fmaf(fmaxf((acc0[tl][3] - mu[1]) * rs[1] * gb + bb, 0.f), w1, pb);
            pc = fmaf(fmaxf((acc1[tl][0] - mu[2]) * rs[2] * ga + ba, 0.f), w0, pc);
            pc = fmaf(fmaxf((acc1[tl][1] - mu[2]) * rs[2] * gb + bb, 0.f), w1, pc);
            pd = fmaf(fmaxf((acc1[tl][2] - mu[3]) * rs[3] * ga + ba, 0.f), w0, pd);
            pd = fmaf(fmaxf((acc1[tl][3] - mu[3]) * rs[3] * gb + bb, 0.f), w1, pd);
        }
#pragma unroll
        for (int o = 1; o <= 2; o <<= 1) {
            pa += __shfl_xor_sync(0xffffffffu, pa, o);
            pb += __shfl_xor_sync(0xffffffffu, pb, o);
            pc += __shfl_xor_sync(0xffffffffu, pc, o);
            pd += __shfl_xor_sync(0xffffffffu, pd, o);
        }
        float* pex = (float*)(smem + OFF_PEX);
        if ((lane & 3) == 0) {
            pex[r0 * 4 + nq] = pa;
            pex[r1 * 4 + nq] = pb;
            pex[r2 * 4 + nq] = pc;
            pex[r3 * 4 + nq] = pd;
        }
    }
    __syncthreads();
    if (tid < TE) {
        float* pex = (float*)(smem + OFF_PEX);
        float p = pex[tid * 4] + pex[tid * 4 + 1] + pex[tid * 4 + 2] + pex[tid * 4 + 3] + b3[0];
        int eg = e0 + tid;
        if (eg < E) out[eg] = 1.f / (1.f + expf(-p));
    }
}

extern "C" void kernel_launch(void* const* d_in, const int* in_sizes, int n_in,
                              void* d_out, int out_size)
{
    const float* h   = (const float*)d_in[0];
    const int*   src = (const int*)d_in[1];
    const int*   dst = (const int*)d_in[2];
    const float* W1 = (const float*)d_in[3];  const float* b1 = (const float*)d_in[4];
    const float* g1 = (const float*)d_in[5];  const float* be1 = (const float*)d_in[6];
    const float* W2 = (const float*)d_in[7];  const float* b2 = (const float*)d_in[8];
    const float* g2 = (const float*)d_in[9];  const float* be2 = (const float*)d_in[10];
    const float* W3 = (const float*)d_in[11]; const float* b3 = (const float*)d_in[12];

    int E  = in_sizes[1];
    int Nn = in_sizes[0] / DD;

    prep_kernel<<<(8192 + 16384 + 255) / 256, 256>>>(W1, W2);

    cudaFuncSetAttribute(mlp_mma_kernel,
                         cudaFuncAttributeMaxDynamicSharedMemorySize, SMEM_BYTES);
    int grid = (E + TE - 1) / TE;
    mlp_mma_kernel<<<grid, NTHR, SMEM_BYTES>>>(
        h, src, dst, b1, g1, be1, b2, g2, be2, W3, b3,
        (float*)d_out, E, Nn);
}

// round 17
// speedup vs baseline: 1.0743x; 1.0026x over previous
#include <cuda_runtime.h>
#include <cuda_fp16.h>
#include <math.h>
#include <stdint.h>

#define NTHR 256
#define TE   64
#define DD   128
#define HH   256
#define EPSLN 1e-5f

// ---------------- smem layout (byte offsets) ----------------
#define OFF_B1S   0
#define OFF_G1S   1024
#define OFF_BE1S  2048
#define OFF_B2S   3072
#define OFF_G2S   4096
#define OFF_BE2S  5120
#define OFF_W3S   6144
#define OFF_LNEX  7168      // 64 rows x 4 quarters x float2 = 2048
#define OFF_PEX   9216      // 64 x 4 x float = 1024
#define TILES     10240
// phase 1: A1 (64x128 fp16, row stride 68 words = 272 B) ; B1 blob
#define A1S   (TILES)                  // 17408
#define B1S   (TILES + 17408)          // 65536 -> ends TILES+82944
// phase 2 (aliases phase 1): A2 (64x256 fp16, stride 132 words = 528 B) ; B2 double buffer
#define A2S    (TILES)                 // 33792
#define B2BUF0 (TILES + 33792)         // 16384
#define B2BUF1 (TILES + 50176)         // 16384 -> ends TILES+66560
#define SMEM_BYTES (TILES + 82944)     // 93184  (x2 CTAs = 186368 <= 228KB)

// fragment-ordered fp16 weight blobs:
// W1 blob slot = ((ntile*8 + kstep)*32 + lane) -> 8 bytes
//   {W[n][k0],W[n][k0+1], W[n][k0+8],W[n][k0+9]}, n = ntile*8 + lane/4, k0 = kstep*16 + (lane%4)*2
__device__ __align__(16) unsigned char g_W1f[65536];
// W2 blob: [kchunk 8][ntile 32][kstep 2][lane 32] x 8B (chunk = K 32)
__device__ __align__(16) unsigned char g_W2f[131072];

__device__ __forceinline__ uint32_t pack_f16x2(float a, float b) {
    __half2 h = __floats2half2_rn(a, b);
    return *reinterpret_cast<uint32_t*>(&h);
}

__device__ __forceinline__ void mma_f16(float d[4], const uint32_t a[4], const uint32_t b[2]) {
    asm volatile(
        "mma.sync.aligned.m16n8k16.row.col.f32.f16.f16.f32 "
        "{%0,%1,%2,%3}, {%4,%5,%6,%7}, {%8,%9}, {%0,%1,%2,%3};"
        : "+f"(d[0]), "+f"(d[1]), "+f"(d[2]), "+f"(d[3])
        : "r"(a[0]), "r"(a[1]), "r"(a[2]), "r"(a[3]), "r"(b[0]), "r"(b[1]));
}

__device__ __forceinline__ void ldsm_x4(uint32_t a[4], uint32_t saddr) {
    asm volatile("ldmatrix.sync.aligned.m8n8.x4.shared.b16 {%0,%1,%2,%3}, [%4];"
                 : "=r"(a[0]), "=r"(a[1]), "=r"(a[2]), "=r"(a[3]) : "r"(saddr));
}

__device__ __forceinline__ void cp16(uint32_t dst_smem, const void* gsrc) {
    asm volatile("cp.async.cg.shared.global [%0], [%1], 16;" :: "r"(dst_smem), "l"(gsrc));
}
#define CP_COMMIT() asm volatile("cp.async.commit_group;" ::: "memory")
#define CP_WAIT(N)  asm volatile("cp.async.wait_group %0;" :: "n"(N) : "memory")

// ---------------- prep: repack weights into fragment-ordered fp16 blobs ----------------
__global__ void prep_kernel(const float* __restrict__ W1, const float* __restrict__ W2) {
    int i = blockIdx.x * blockDim.x + threadIdx.x;
    if (i < 8192) {                                    // W1 [256n][128k], 32 nt x 8 ks
        int nt = i >> 8, ks = (i >> 5) & 7, lane = i & 31;
        int n = nt * 8 + (lane >> 2);
        int k0 = ks * 16 + (lane & 3) * 2;
        const float* w = W1 + n * 128 + k0;
        ((uint2*)g_W1f)[i] = make_uint2(pack_f16x2(w[0], w[1]), pack_f16x2(w[8], w[9]));
    } else if (i < 8192 + 16384) {                     // W2 [256n][256k], 8 kc x 32 nt x 2 ks
        int j = i - 8192;
        int kc = j >> 11, nt = (j >> 6) & 31, ks = (j >> 5) & 1, lane = j & 31;
        int n = nt * 8 + (lane >> 2);
        int k0 = kc * 32 + ks * 16 + (lane & 3) * 2;
        const float* w = W2 + n * 256 + k0;
        ((uint2*)g_W2f)[j] = make_uint2(pack_f16x2(w[0], w[1]), pack_f16x2(w[8], w[9]));
    }
}

// ---------------- main ----------------
__global__ void __launch_bounds__(NTHR, 2)
mlp_mma_kernel(const float* __restrict__ h,
               const int* __restrict__ src, const int* __restrict__ dst,
               const float* __restrict__ b1, const float* __restrict__ g1, const float* __restrict__ be1,
               const float* __restrict__ b2, const float* __restrict__ g2, const float* __restrict__ be2,
               const float* __restrict__ W3, const float* __restrict__ b3,
               float* __restrict__ out, int E, int Nn)
{
    extern __shared__ __align__(16) char smem[];
    const int tid   = threadIdx.x;
    const int wid   = tid >> 5;
    const int lane  = tid & 31;
    const int rowt  = wid & 1;          // row group: rows [rowt*32, rowt*32+32)
    const int nq    = wid >> 1;         // col quarter: cols [nq*64, nq*64+64)
    const int e0    = blockIdx.x * TE;
    const uint32_t sbase = (uint32_t)__cvta_generic_to_shared(smem);

    // ldmatrix lane addressing
    const int lrow = (((lane >> 3) & 1) << 3) + (lane & 7);
    const int lkb  = ((lane >> 4) << 4);

    // --- async-stage B1 blob (65536 B) ---
    {
        uint32_t dh = sbase + B1S;
#pragma unroll
        for (int i = 0; i < 16; i++)
            cp16(dh + (tid + i * NTHR) * 16, (const char*)g_W1f + (tid + i * NTHR) * 16);
        CP_COMMIT();
    }

    // --- params (256 threads, 256 entries each) ---
    {
        ((float*)(smem + OFF_B1S))[tid]  = b1[tid];
        ((float*)(smem + OFF_G1S))[tid]  = g1[tid];
        ((float*)(smem + OFF_BE1S))[tid] = be1[tid];
        ((float*)(smem + OFF_B2S))[tid]  = b2[tid];
        ((float*)(smem + OFF_G2S))[tid]  = g2[tid];
        ((float*)(smem + OFF_BE2S))[tid] = be2[tid];
        ((float*)(smem + OFF_W3S))[tid]  = W3[tid];
    }

    // --- gather x = h[src]*h[dst] -> fp16, A1 row-major (stride 68 words) ---
    {
        int row = tid >> 2, q = tid & 3;          // 64 rows x 4 quarters
        int eg = e0 + row;
        int si = 0, di = 0;
        if (eg < E) { si = src[eg]; di = dst[eg]; }
        if ((unsigned)si >= (unsigned)Nn) si = 0;
        if ((unsigned)di >= (unsigned)Nn) di = 0;
        const float4* ps = (const float4*)(h + (size_t)si * DD) + q * 8;
        const float4* pd = (const float4*)(h + (size_t)di * DD) + q * 8;
        uint32_t* oh = (uint32_t*)(smem + A1S) + row * 68 + q * 16;
#pragma unroll
        for (int i = 0; i < 8; i++) {
            float4 a = ps[i], b = pd[i];
            oh[i * 2]     = pack_f16x2(a.x * b.x, a.y * b.y);
            oh[i * 2 + 1] = pack_f16x2(a.z * b.z, a.w * b.w);
        }
    }
    CP_WAIT(0);
    __syncthreads();

    float acc0[8][4], acc1[8][4];
#pragma unroll
    for (int t = 0; t < 8; t++) {
        acc0[t][0]=acc0[t][1]=acc0[t][2]=acc0[t][3]=0.f;
        acc1[t][0]=acc1[t][1]=acc1[t][2]=acc1[t][3]=0.f;
    }

    const int rbase = rowt * 32 + (lane >> 2);

    // ---- layer 1: K=128, 8 ksteps, fp16, ldmatrix A (2x software-pipelined) ----
    {
        const uint32_t aA0 = sbase + A1S + (uint32_t)(rowt * 32 + lrow) * 272 + lkb;
        const uint32_t aA1 = aA0 + 16 * 272;
#pragma unroll 2
        for (int ks = 0; ks < 8; ks++) {
            uint32_t a0[4], a1[4];
            ldsm_x4(a0, aA0 + ks * 32);
            ldsm_x4(a1, aA1 + ks * 32);
#pragma unroll
            for (int tl = 0; tl < 8; tl++) {
                int nt = nq * 8 + tl;
                uint2 bh = *(const uint2*)(smem + B1S + (size_t)((nt * 8 + ks) * 32 + lane) * 8);
                mma_f16(acc0[tl], a0, (const uint32_t*)&bh);
                mma_f16(acc1[tl], a1, (const uint32_t*)&bh);
            }
        }
    }

    const int r0 = rbase, r1 = rbase + 8, r2 = rbase + 16, r3 = rbase + 24;
    const float* b1s  = (const float*)(smem + OFF_B1S);
    const float* g1s  = (const float*)(smem + OFF_G1S);
    const float* be1s = (const float*)(smem + OFF_BE1S);
    float2* lnex = (float2*)(smem + OFF_LNEX);

    // ---- epilogue 1: bias + partial LN stats (per col-quarter) ----
    {
        float sa=0.f,s2a=0.f, sb=0.f,s2b=0.f, sc=0.f,s2c=0.f, sd=0.f,s2d=0.f;
#pragma unroll
        for (int tl = 0; tl < 8; tl++) {
            int c0 = nq * 64 + tl * 8 + (lane & 3) * 2;
            float bb0 = b1s[c0], bb1 = b1s[c0 + 1];
            acc0[tl][0] += bb0; acc0[tl][1] += bb1; acc0[tl][2] += bb0; acc0[tl][3] += bb1;
            acc1[tl][0] += bb0; acc1[tl][1] += bb1; acc1[tl][2] += bb0; acc1[tl][3] += bb1;
            sa += acc0[tl][0] + acc0[tl][1]; s2a += acc0[tl][0]*acc0[tl][0] + acc0[tl][1]*acc0[tl][1];
            sb += acc0[tl][2] + acc0[tl][3]; s2b += acc0[tl][2]*acc0[tl][2] + acc0[tl][3]*acc0[tl][3];
            sc += acc1[tl][0] + acc1[tl][1]; s2c += acc1[tl][0]*acc1[tl][0] + acc1[tl][1]*acc1[tl][1];
            sd += acc1[tl][2] + acc1[tl][3]; s2d += acc1[tl][2]*acc1[tl][2] + acc1[tl][3]*acc1[tl][3];
        }
#pragma unroll
        for (int o = 1; o <= 2; o <<= 1) {
            sa += __shfl_xor_sync(0xffffffffu, sa, o);  s2a += __shfl_xor_sync(0xffffffffu, s2a, o);
            sb += __shfl_xor_sync(0xffffffffu, sb, o);  s2b += __shfl_xor_sync(0xffffffffu, s2b, o);
            sc += __shfl_xor_sync(0xffffffffu, sc, o);  s2c += __shfl_xor_sync(0xffffffffu, s2c, o);
            sd += __shfl_xor_sync(0xffffffffu, sd, o);  s2d += __shfl_xor_sync(0xffffffffu, s2d, o);
        }
        if ((lane & 3) == 0) {
            lnex[r0 * 4 + nq] = make_float2(sa, s2a);
            lnex[r1 * 4 + nq] = make_float2(sb, s2b);
            lnex[r2 * 4 + nq] = make_float2(sc, s2c);
            lnex[r3 * 4 + nq] = make_float2(sd, s2d);
        }
    }
    __syncthreads();   // A1/B1 now dead

    // prefetch W2 chunk 0 into buf0
    {
        uint32_t d0 = sbase + B2BUF0;
#pragma unroll
        for (int i = 0; i < 4; i++)
            cp16(d0 + (tid + i * NTHR) * 16, (const char*)g_W2f + (tid + i * NTHR) * 16);
        CP_COMMIT();
    }

    // ---- LN1 transform + ReLU -> A2 fp16 (stride 132 words) ----
    {
        float mu[4], rs[4];
        int rr[4] = {r0, r1, r2, r3};
#pragma unroll
        for (int k = 0; k < 4; k++) {
            float2 q0 = lnex[rr[k] * 4 + 0], q1 = lnex[rr[k] * 4 + 1];
            float2 q2 = lnex[rr[k] * 4 + 2], q3 = lnex[rr[k] * 4 + 3];
            float s  = q0.x + q1.x + q2.x + q3.x;
            float s2 = q0.y + q1.y + q2.y + q3.y;
            mu[k] = s * (1.f / HH);
            rs[k] = rsqrtf(s2 * (1.f / HH) - mu[k] * mu[k] + EPSLN);
        }
        uint32_t* A2w = (uint32_t*)(smem + A2S);
#pragma unroll
        for (int tl = 0; tl < 8; tl++) {
            int c0 = nq * 64 + tl * 8 + (lane & 3) * 2;
            float ga = g1s[c0], gb = g1s[c0 + 1], ba = be1s[c0], bb = be1s[c0 + 1];
            int w = c0 >> 1;
            A2w[r0 * 132 + w] = pack_f16x2(
                fmaxf((acc0[tl][0] - mu[0]) * rs[0] * ga + ba, 0.f),
                fmaxf((acc0[tl][1] - mu[0]) * rs[0] * gb + bb, 0.f));
            A2w[r1 * 132 + w] = pack_f16x2(
                fmaxf((acc0[tl][2] - mu[1]) * rs[1] * ga + ba, 0.f),
                fmaxf((acc0[tl][3] - mu[1]) * rs[1] * gb + bb, 0.f));
            A2w[r2 * 132 + w] = pack_f16x2(
                fmaxf((acc1[tl][0] - mu[2]) * rs[2] * ga + ba, 0.f),
                fmaxf((acc1[tl][1] - mu[2]) * rs[2] * gb + bb, 0.f));
            A2w[r3 * 132 + w] = pack_f16x2(
                fmaxf((acc1[tl][2] - mu[3]) * rs[3] * ga + ba, 0.f),
                fmaxf((acc1[tl][3] - mu[3]) * rs[3] * gb + bb, 0.f));
        }
    }

#pragma unroll
    for (int t = 0; t < 8; t++) {
        acc0[t][0]=acc0[t][1]=acc0[t][2]=acc0[t][3]=0.f;
        acc1[t][0]=acc1[t][1]=acc1[t][2]=acc1[t][3]=0.f;
    }

    // ---- layer 2: K=256 in 8 chunks of 32, double-buffered cp.async ----
    {
        const uint32_t aB0 = sbase + A2S + (uint32_t)(rowt * 32 + lrow) * 528 + lkb;
        const uint32_t aB1 = aB0 + 16 * 528;
#pragma unroll 1
        for (int kc = 0; kc < 8; kc++) {
            __syncthreads();   // prior reads of the buffer being overwritten are done
            if (kc < 7) {
                uint32_t d = sbase + (((kc + 1) & 1) ? B2BUF1 : B2BUF0);
                const char* sh = (const char*)g_W2f + (kc + 1) * 16384;
#pragma unroll
                for (int i = 0; i < 4; i++)
                    cp16(d + (tid + i * NTHR) * 16, sh + (tid + i * NTHR) * 16);
                CP_COMMIT();
                CP_WAIT(1);    // chunk kc has landed
            } else {
                CP_WAIT(0);
            }
            __syncthreads();   // chunk kc visible to all warps
            const char* buf = smem + ((kc & 1) ? B2BUF1 : B2BUF0);
#pragma unroll
            for (int ks = 0; ks < 2; ks++) {
                int gk = kc * 2 + ks;
                uint32_t a0[4], a1[4];
                ldsm_x4(a0, aB0 + gk * 32);
                ldsm_x4(a1, aB1 + gk * 32);
#pragma unroll
                for (int tl = 0; tl < 8; tl++) {
                    int nt = nq * 8 + tl;
                    uint2 bh = *(const uint2*)(buf + (size_t)((nt * 2 + ks) * 32 + lane) * 8);
                    mma_f16(acc0[tl], a0, (const uint32_t*)&bh);
                    mma_f16(acc1[tl], a1, (const uint32_t*)&bh);
                }
            }
        }
    }

    // ---- epilogue 2: bias + partial LN stats ----
    const float* b2s  = (const float*)(smem + OFF_B2S);
    const float* g2s  = (const float*)(smem + OFF_G2S);
    const float* be2s = (const float*)(smem + OFF_BE2S);
    const float* w3s  = (const float*)(smem + OFF_W3S);
    {
        float sa=0.f,s2a=0.f, sb=0.f,s2b=0.f, sc=0.f,s2c=0.f, sd=0.f,s2d=0.f;
#pragma unroll
        for (int tl = 0; tl < 8; tl++) {
            int c0 = nq * 64 + tl * 8 + (lane & 3) * 2;
            float bb0 = b2s[c0], bb1 = b2s[c0 + 1];
            acc0[tl][0] += bb0; acc0[tl][1] += bb1; acc0[tl][2] += bb0; acc0[tl][3] += bb1;
            acc1[tl][0] += bb0; acc1[tl][1] += bb1; acc1[tl][2] += bb0; acc1[tl][3] += bb1;
            sa += acc0[tl][0] + acc0[tl][1]; s2a += acc0[tl][0]*acc0[tl][0] + acc0[tl][1]*acc0[tl][1];
            sb += acc0[tl][2] + acc0[tl][3]; s2b += acc0[tl][2]*acc0[tl][2] + acc0[tl][3]*acc0[tl][3];
            sc += acc1[tl][0] + acc1[tl][1]; s2c += acc1[tl][0]*acc1[tl][0] + acc1[tl][1]*acc1[tl][1];
            sd += acc1[tl][2] + acc1[tl][3]; s2d += acc1[tl][2]*acc1[tl][2] + acc1[tl][3]*acc1[tl][3];
        }
#pragma unroll
        for (int o = 1; o <= 2; o <<= 1) {
            sa += __shfl_xor_sync(0xffffffffu, sa, o);  s2a += __shfl_xor_sync(0xffffffffu, s2a, o);
            sb += __shfl_xor_sync(0xffffffffu, sb, o);  s2b += __shfl_xor_sync(0xffffffffu, s2b, o);
            sc += __shfl_xor_sync(0xffffffffu, sc, o);  s2c += __shfl_xor_sync(0xffffffffu, s2c, o);
            sd += __shfl_xor_sync(0xffffffffu, sd, o);  s2d += __shfl_xor_sync(0xffffffffu, s2d, o);
        }
        if ((lane & 3) == 0) {
            lnex[r0 * 4 + nq] = make_float2(sa, s2a);
            lnex[r1 * 4 + nq] = make_float2(sb, s2b);
            lnex[r2 * 4 + nq] = make_float2(sc, s2c);
            lnex[r3 * 4 + nq] = make_float2(sd, s2d);
        }
    }
    __syncthreads();
    // ---- LN2 + ReLU + dot W3 partials ----
    {
        float mu[4], rs[4];
        int rr[4] = {r0, r1, r2, r3};
#pragma unroll
        for (int k = 0; k < 4; k++) {
            float2 q0 = lnex[rr[k] * 4 + 0], q1 = lnex[rr[k] * 4 + 1];
            float2 q2 = lnex[rr[k] * 4 + 2], q3 = lnex[rr[k] * 4 + 3];
            float s  = q0.x + q1.x + q2.x + q3.x;
            float s2 = q0.y + q1.y + q2.y + q3.y;
            mu[k] = s * (1.f / HH);
            rs[k] = rsqrtf(s2 * (1.f / HH) - mu[k] * mu[k] + EPSLN);
        }
        float pa = 0.f, pb = 0.f, pc = 0.f, pd = 0.f;
#pragma unroll
        for (int tl = 0; tl < 8; tl++) {
            int c0 = nq * 64 + tl * 8 + (lane & 3) * 2;
            float ga = g2s[c0], gb = g2s[c0 + 1], ba = be2s[c0], bb = be2s[c0 + 1];
            float w0 = w3s[c0], w1 = w3s[c0 + 1];
            pa = fmaf(fmaxf((acc0[tl][0] - mu[0]) * rs[0] * ga + ba, 0.f), w0, pa);
            pa = fmaf(fmaxf((acc0[tl][1] - mu[0]) * rs[0] * gb + bb, 0.f), w1, pa);
            pb = fmaf(fmaxf((acc0[tl][2] - mu[1]) * rs[1] * ga + ba, 0.f), w0, pb);
            pb = fmaf(fmaxf((acc0[tl][3] - mu[1]) * rs[1] * gb + bb, 0.f), w1, pb);
            pc = fmaf(fmaxf((acc1[tl][0] - mu[2]) * rs[2] * ga + ba, 0.f), w0, pc);
            pc = fmaf(fmaxf((acc1[tl][1] - mu[2]) * rs[2] * gb + bb, 0.f), w1, pc);
            pd = fmaf(fmaxf((acc1[tl][2] - mu[3]) * rs[3] * ga + ba, 0.f), w0, pd);
            pd = fmaf(fmaxf((acc1[tl][3] - mu[3]) * rs[3] * gb + bb, 0.f), w1, pd);
        }
#pragma unroll
        for (int o = 1; o <= 2; o <<= 1) {
            pa += __shfl_xor_sync(0xffffffffu, pa, o);
            pb += __shfl_xor_sync(0xffffffffu, pb, o);
            pc += __shfl_xor_sync(0xffffffffu, pc, o);
            pd += __shfl_xor_sync(0xffffffffu, pd, o);
        }
        float* pex = (float*)(smem + OFF_PEX);
        if ((lane & 3) == 0) {
            pex[r0 * 4 + nq] = pa;
            pex[r1 * 4 + nq] = pb;
            pex[r2 * 4 + nq] = pc;
            pex[r3 * 4 + nq] = pd;
        }
    }
    __syncthreads();
    if (tid < TE) {
        float* pex = (float*)(smem + OFF_PEX);
        float p = pex[tid * 4] + pex[tid * 4 + 1] + pex[tid * 4 + 2] + pex[tid * 4 + 3] + b3[0];
        int eg = e0 + tid;
        if (eg < E) out[eg] = 1.f / (1.f + __expf(-p));
    }
}

extern "C" void kernel_launch(void* const* d_in, const int* in_sizes, int n_in,
                              void* d_out, int out_size)
{
    const float* h   = (const float*)d_in[0];
    const int*   src = (const int*)d_in[1];
    const int*   dst = (const int*)d_in[2];
    const float* W1 = (const float*)d_in[3];  const float* b1 = (const float*)d_in[4];
    const float* g1 = (const float*)d_in[5];  const float* be1 = (const float*)d_in[6];
    const float* W2 = (const float*)d_in[7];  const float* b2 = (const float*)d_in[8];
    const float* g2 = (const float*)d_in[9];  const float* be2 = (const float*)d_in[10];
    const float* W3 = (const float*)d_in[11]; const float* b3 = (const float*)d_in[12];

    int E  = in_sizes[1];
    int Nn = in_sizes[0] / DD;

    prep_kernel<<<(8192 + 16384 + 255) / 256, 256>>>(W1, W2);

    cudaFuncSetAttribute(mlp_mma_kernel,
                         cudaFuncAttributeMaxDynamicSharedMemorySize, SMEM_BYTES);
    int grid = (E + TE - 1) / TE;
    mlp_mma_kernel<<<grid, NTHR, SMEM_BYTES>>>(
        h, src, dst, b1, g1, be1, b2, g2, be2, W3, b3,
        (float*)d_out, E, Nn);
}